// round 2
// baseline (speedup 1.0000x reference)
#include <cuda_runtime.h>
#include <math.h>

// Problem constants (fixed by the reference setup)
#define BB 4
#define CC 32
#define PP 262144       // 512*512 pixels per image
#define NI 100          // n_instances
#define CHUNK 2048      // pixels per block
#define TPB 256
#define PPT (CHUNK/TPB) // 8 pixels per thread
#define CHUNKS_PER_IMG (PP/CHUNK)   // 128
#define NBLK (BB*CHUNKS_PER_IMG)    // 512

// Scratch (no device allocation allowed -> __device__ globals)
__device__ float g_sums[BB*CC*NI];   // [b][c][k]
__device__ int   g_counts[BB*NI];
__device__ float g_means[BB*CC*NI];  // [b][c][k]
__device__ float g_invc[BB*NI];
__device__ float g_var[BB];
__device__ float g_dist[BB];
__device__ float g_reg[BB];

__global__ void zero_k() {
    int i = blockIdx.x * blockDim.x + threadIdx.x;
    if (i < BB*CC*NI) g_sums[i] = 0.f;
    if (i < BB*NI)    g_counts[i] = 0;
    if (i < BB) { g_var[i] = 0.f; g_dist[i] = 0.f; g_reg[i] = 0.f; }
}

// -------- Pass 1: per-label sums + counts --------
__global__ __launch_bounds__(TPB) void pass1_k(const float* __restrict__ in,
                                               const int* __restrict__ tgt) {
    __shared__ float ssum[CC*NI];   // [c*100+k] -> bank = (c*100+k)&31, label-randomized
    __shared__ int   scnt[NI];

    int blk   = blockIdx.x;
    int b     = blk >> 7;           // /128
    int chunk = blk & 127;
    int p0    = chunk * CHUNK;
    int t     = threadIdx.x;

    for (int i = t; i < CC*NI; i += TPB) ssum[i] = 0.f;
    for (int i = t; i < NI;    i += TPB) scnt[i] = 0;
    __syncthreads();

    int lbl[PPT];
    const int* tg = tgt + (size_t)b * PP + p0;
#pragma unroll
    for (int k = 0; k < PPT; k++) lbl[k] = tg[t + k*TPB];
#pragma unroll
    for (int k = 0; k < PPT; k++) atomicAdd(&scnt[lbl[k]], 1);

    const float* base = in + (size_t)b * CC * PP + p0;
    for (int c = 0; c < CC; c++) {
        const float* pc = base + (size_t)c * PP;
        float v[PPT];
#pragma unroll
        for (int k = 0; k < PPT; k++) v[k] = pc[t + k*TPB];   // MLP batch of 8 loads
#pragma unroll
        for (int k = 0; k < PPT; k++) atomicAdd(&ssum[c*NI + lbl[k]], v[k]);
    }
    __syncthreads();

    float* gs = g_sums + (size_t)b * CC * NI;
    for (int i = t; i < CC*NI; i += TPB) atomicAdd(&gs[i], ssum[i]);
    int* gc = g_counts + b * NI;
    for (int i = t; i < NI; i += TPB) atomicAdd(&gc[i], scnt[i]);
}

// -------- Middle: means, inv-counts, reg term, pairwise distance term --------
// grid = (4, 16)
__global__ __launch_bounds__(TPB) void means_k() {
    __shared__ float sm[NI*33];     // [k*33+c] padded: pairwise reads conflict-free
    __shared__ float red[TPB/32];

    int b = blockIdx.x;
    int t = threadIdx.x;

    for (int i = t; i < CC*NI; i += TPB) {
        int c = i / NI;
        int k = i - c * NI;
        int cnt = g_counts[b*NI + k];
        float m = (cnt > 0) ? g_sums[(size_t)b*CC*NI + i] / (float)cnt : 0.f;
        sm[k*33 + c] = m;
        if (blockIdx.y == 0) g_means[(size_t)b*CC*NI + i] = m;
    }
    if (blockIdx.y == 0) {
        for (int k = t; k < NI; k += TPB) {
            int cnt = g_counts[b*NI + k];
            g_invc[b*NI + k] = (cnt > 0) ? 1.f / (float)cnt : 0.f;
        }
    }
    __syncthreads();

    // reg term: sum_k ||mean_k||
    if (blockIdx.y == 0 && t < NI) {
        float s = 0.f;
#pragma unroll
        for (int c = 0; c < CC; c++) { float m = sm[t*33 + c]; s = fmaf(m, m, s); }
        atomicAdd(&g_reg[b], sqrtf(s));
    }

    // distance term over all (i,j), i != j
    float local = 0.f;
    for (int idx = blockIdx.y * TPB + t; idx < NI*NI; idx += gridDim.y * TPB) {
        int i = idx / NI;
        int j = idx - i * NI;
        if (i != j) {
            float d2 = 0.f;
#pragma unroll
            for (int c = 0; c < CC; c++) {
                float d = sm[i*33 + c] - sm[j*33 + c];
                d2 = fmaf(d, d, d2);
            }
            float d = (d2 > 0.f) ? sqrtf(d2) : 1.f;   // matches jnp.where(d2>0, d2, 1)
            float h = fmaxf(4.f - d, 0.f);            // 2*DELTA_DIST = 4
            local += h * h;
        }
    }
    // block reduce
#pragma unroll
    for (int o = 16; o > 0; o >>= 1) local += __shfl_down_sync(0xffffffffu, local, o);
    if ((t & 31) == 0) red[t >> 5] = local;
    __syncthreads();
    if (t < 32) {
        float v = (t < TPB/32) ? red[t] : 0.f;
#pragma unroll
        for (int o = 16; o > 0; o >>= 1) v += __shfl_down_sync(0xffffffffu, v, o);
        if (t == 0) atomicAdd(&g_dist[b], v);
    }
}

// -------- Pass 2: variance term (register-resident per-pixel accumulators) --------
__global__ __launch_bounds__(TPB) void pass2_k(const float* __restrict__ in,
                                               const int* __restrict__ tgt) {
    __shared__ float smean[CC*NI];  // [c*100+k]
    __shared__ float sinv[NI];
    __shared__ float red[TPB/32];

    int blk   = blockIdx.x;
    int b     = blk >> 7;
    int chunk = blk & 127;
    int p0    = chunk * CHUNK;
    int t     = threadIdx.x;

    for (int i = t; i < CC*NI; i += TPB) smean[i] = g_means[(size_t)b*CC*NI + i];
    for (int i = t; i < NI;    i += TPB) sinv[i]  = g_invc[b*NI + i];
    __syncthreads();

    int lbl[PPT];
    const int* tg = tgt + (size_t)b * PP + p0;
#pragma unroll
    for (int k = 0; k < PPT; k++) lbl[k] = tg[t + k*TPB];

    float acc[PPT];
#pragma unroll
    for (int k = 0; k < PPT; k++) acc[k] = 0.f;

    const float* base = in + (size_t)b * CC * PP + p0;
    for (int c = 0; c < CC; c++) {
        const float* pc = base + (size_t)c * PP;
        float v[PPT];
#pragma unroll
        for (int k = 0; k < PPT; k++) v[k] = pc[t + k*TPB];
#pragma unroll
        for (int k = 0; k < PPT; k++) {
            float d = v[k] - smean[c*NI + lbl[k]];
            acc[k] = fmaf(d, d, acc[k]);
        }
    }

    float local = 0.f;
#pragma unroll
    for (int k = 0; k < PPT; k++) {
        float n = sqrtf(acc[k]);
        float h = fmaxf(n - 0.75f, 0.f);   // DELTA_VAR
        local += h * h * sinv[lbl[k]];
    }
#pragma unroll
    for (int o = 16; o > 0; o >>= 1) local += __shfl_down_sync(0xffffffffu, local, o);
    if ((t & 31) == 0) red[t >> 5] = local;
    __syncthreads();
    if (t < 32) {
        float v = (t < TPB/32) ? red[t] : 0.f;
#pragma unroll
        for (int o = 16; o > 0; o >>= 1) v += __shfl_down_sync(0xffffffffu, v, o);
        if (t == 0) atomicAdd(&g_var[b], v);
    }
}

// -------- Final: combine terms, mean over batch --------
__global__ void final_k(float* __restrict__ out) {
    if (threadIdx.x == 0 && blockIdx.x == 0) {
        float s = 0.f;
#pragma unroll
        for (int b = 0; b < BB; b++) {
            float var_term  = g_var[b]  * (1.f / (float)NI);
            float dist_term = g_dist[b] * (1.f / (float)(NI * (NI - 1)));
            float reg_term  = g_reg[b]  * (1.f / (float)NI);
            s += var_term + dist_term + 0.001f * reg_term;   // ALPHA=BETA=1, GAMMA=1e-3
        }
        out[0] = s * (1.f / (float)BB);
    }
}

extern "C" void kernel_launch(void* const* d_in, const int* in_sizes, int n_in,
                              void* d_out, int out_size) {
    const float* in  = (const float*)d_in[0];
    const int*   tgt = (const int*)d_in[1];
    float*       out = (float*)d_out;
    (void)in_sizes; (void)n_in; (void)out_size;

    zero_k<<<(BB*CC*NI + TPB - 1) / TPB, TPB>>>();
    pass1_k<<<NBLK, TPB>>>(in, tgt);
    dim3 g(BB, 16);
    means_k<<<g, TPB>>>();
    pass2_k<<<NBLK, TPB>>>(in, tgt);
    final_k<<<1, 32>>>(out);
}

// round 3
// speedup vs baseline: 1.1494x; 1.1494x over previous
#include <cuda_runtime.h>
#include <math.h>

// Problem constants (fixed by the reference setup)
#define BB 4
#define CC 32
#define PP 262144       // 512*512 pixels per image
#define NI 100          // n_instances
#define CHUNK 2048      // pixels per block
#define TPB 512
#define PPT 4           // pixels (one float4) per thread
#define CHUNKS_PER_IMG (PP/CHUNK)   // 128
#define NBLK (BB*CHUNKS_PER_IMG)    // 512

// Scratch (no device allocation allowed -> __device__ globals)
__device__ float g_sums[BB*CC*NI];   // [b][c][k]
__device__ int   g_counts[BB*NI];
__device__ float g_means[BB*CC*NI];  // [b][c][k]
__device__ float g_invc[BB*NI];
__device__ float g_var[BB];
__device__ float g_dist[BB];
__device__ float g_reg[BB];

__global__ void zero_k() {
    int i = blockIdx.x * blockDim.x + threadIdx.x;
    if (i < BB*CC*NI) g_sums[i] = 0.f;
    if (i < BB*NI)    g_counts[i] = 0;
    if (i < BB) { g_var[i] = 0.f; g_dist[i] = 0.f; g_reg[i] = 0.f; }
}

// -------- Pass 1: per-label sums + counts --------
__global__ __launch_bounds__(TPB) void pass1_k(const float* __restrict__ in,
                                               const int* __restrict__ tgt) {
    __shared__ float ssum[CC*NI];   // [c*100+k] -> bank label-randomized
    __shared__ int   scnt[NI];

    int blk   = blockIdx.x;
    int b     = blk >> 7;           // /128
    int chunk = blk & 127;
    int p0    = chunk * CHUNK;
    int t     = threadIdx.x;

    for (int i = t; i < CC*NI; i += TPB) ssum[i] = 0.f;
    for (int i = t; i < NI;    i += TPB) scnt[i] = 0;
    __syncthreads();

    const int4* tg = (const int4*)(tgt + (size_t)b * PP + p0);
    int4 lv = tg[t];
    int lbl[PPT] = {lv.x, lv.y, lv.z, lv.w};
#pragma unroll
    for (int k = 0; k < PPT; k++) atomicAdd(&scnt[lbl[k]], 1);

    const float* base = in + (size_t)b * CC * PP + p0;
#pragma unroll 4
    for (int c = 0; c < CC; c++) {
        const float4* pc = (const float4*)(base + (size_t)c * PP);
        float4 v = pc[t];
        atomicAdd(&ssum[c*NI + lbl[0]], v.x);
        atomicAdd(&ssum[c*NI + lbl[1]], v.y);
        atomicAdd(&ssum[c*NI + lbl[2]], v.z);
        atomicAdd(&ssum[c*NI + lbl[3]], v.w);
    }
    __syncthreads();

    float* gs = g_sums + (size_t)b * CC * NI;
    for (int i = t; i < CC*NI; i += TPB) atomicAdd(&gs[i], ssum[i]);
    int* gc = g_counts + b * NI;
    for (int i = t; i < NI; i += TPB) atomicAdd(&gc[i], scnt[i]);
}

// -------- Middle: means, inv-counts, reg term, pairwise distance term --------
// grid = (4, 16), block = 256
__global__ __launch_bounds__(256) void means_k() {
    __shared__ float sm[NI*33];     // [k*33+c] padded: pairwise reads conflict-free
    __shared__ float red[8];

    int b = blockIdx.x;
    int t = threadIdx.x;

    for (int i = t; i < CC*NI; i += 256) {
        int c = i / NI;
        int k = i - c * NI;
        int cnt = g_counts[b*NI + k];
        float m = (cnt > 0) ? g_sums[(size_t)b*CC*NI + i] / (float)cnt : 0.f;
        sm[k*33 + c] = m;
        if (blockIdx.y == 0) g_means[(size_t)b*CC*NI + i] = m;
    }
    if (blockIdx.y == 0) {
        for (int k = t; k < NI; k += 256) {
            int cnt = g_counts[b*NI + k];
            g_invc[b*NI + k] = (cnt > 0) ? 1.f / (float)cnt : 0.f;
        }
    }
    __syncthreads();

    // reg term: sum_k ||mean_k||
    if (blockIdx.y == 0 && t < NI) {
        float s = 0.f;
#pragma unroll
        for (int c = 0; c < CC; c++) { float m = sm[t*33 + c]; s = fmaf(m, m, s); }
        atomicAdd(&g_reg[b], sqrtf(s));
    }

    // distance term over all (i,j), i != j
    float local = 0.f;
    for (int idx = blockIdx.y * 256 + t; idx < NI*NI; idx += gridDim.y * 256) {
        int i = idx / NI;
        int j = idx - i * NI;
        if (i != j) {
            float d2 = 0.f;
#pragma unroll
            for (int c = 0; c < CC; c++) {
                float d = sm[i*33 + c] - sm[j*33 + c];
                d2 = fmaf(d, d, d2);
            }
            float d = (d2 > 0.f) ? sqrtf(d2) : 1.f;   // matches jnp.where(d2>0, d2, 1)
            float h = fmaxf(4.f - d, 0.f);            // 2*DELTA_DIST = 4
            local += h * h;
        }
    }
#pragma unroll
    for (int o = 16; o > 0; o >>= 1) local += __shfl_down_sync(0xffffffffu, local, o);
    if ((t & 31) == 0) red[t >> 5] = local;
    __syncthreads();
    if (t < 32) {
        float v = (t < 8) ? red[t] : 0.f;
#pragma unroll
        for (int o = 4; o > 0; o >>= 1) v += __shfl_down_sync(0xffffffffu, v, o);
        if (t == 0) atomicAdd(&g_dist[b], v);
    }
}

// -------- Pass 2: variance term (register-resident per-pixel accumulators) --------
__global__ __launch_bounds__(TPB) void pass2_k(const float* __restrict__ in,
                                               const int* __restrict__ tgt) {
    __shared__ float smean[CC*NI];  // [c*100+k]
    __shared__ float sinv[NI];
    __shared__ float red[TPB/32];

    int blk   = blockIdx.x;
    int b     = blk >> 7;
    int chunk = blk & 127;
    int p0    = chunk * CHUNK;
    int t     = threadIdx.x;

    for (int i = t; i < CC*NI; i += TPB) smean[i] = g_means[(size_t)b*CC*NI + i];
    for (int i = t; i < NI;    i += TPB) sinv[i]  = g_invc[b*NI + i];
    __syncthreads();

    const int4* tg = (const int4*)(tgt + (size_t)b * PP + p0);
    int4 lv = tg[t];
    int lbl[PPT] = {lv.x, lv.y, lv.z, lv.w};

    float acc[PPT];
#pragma unroll
    for (int k = 0; k < PPT; k++) acc[k] = 0.f;

    const float* base = in + (size_t)b * CC * PP + p0;
#pragma unroll 4
    for (int c = 0; c < CC; c++) {
        const float4* pc = (const float4*)(base + (size_t)c * PP);
        float4 v = pc[t];
        float d0 = v.x - smean[c*NI + lbl[0]];
        float d1 = v.y - smean[c*NI + lbl[1]];
        float d2 = v.z - smean[c*NI + lbl[2]];
        float d3 = v.w - smean[c*NI + lbl[3]];
        acc[0] = fmaf(d0, d0, acc[0]);
        acc[1] = fmaf(d1, d1, acc[1]);
        acc[2] = fmaf(d2, d2, acc[2]);
        acc[3] = fmaf(d3, d3, acc[3]);
    }

    float local = 0.f;
#pragma unroll
    for (int k = 0; k < PPT; k++) {
        float n = sqrtf(acc[k]);
        float h = fmaxf(n - 0.75f, 0.f);   // DELTA_VAR
        local += h * h * sinv[lbl[k]];
    }
#pragma unroll
    for (int o = 16; o > 0; o >>= 1) local += __shfl_down_sync(0xffffffffu, local, o);
    if ((t & 31) == 0) red[t >> 5] = local;
    __syncthreads();
    if (t < 32) {
        float v = (t < TPB/32) ? red[t] : 0.f;
#pragma unroll
        for (int o = 16; o > 0; o >>= 1) v += __shfl_down_sync(0xffffffffu, v, o);
        if (t == 0) atomicAdd(&g_var[b], v);
    }
}

// -------- Final: combine terms, mean over batch --------
__global__ void final_k(float* __restrict__ out) {
    if (threadIdx.x == 0 && blockIdx.x == 0) {
        float s = 0.f;
#pragma unroll
        for (int b = 0; b < BB; b++) {
            float var_term  = g_var[b]  * (1.f / (float)NI);
            float dist_term = g_dist[b] * (1.f / (float)(NI * (NI - 1)));
            float reg_term  = g_reg[b]  * (1.f / (float)NI);
            s += var_term + dist_term + 0.001f * reg_term;   // ALPHA=BETA=1, GAMMA=1e-3
        }
        out[0] = s * (1.f / (float)BB);
    }
}

extern "C" void kernel_launch(void* const* d_in, const int* in_sizes, int n_in,
                              void* d_out, int out_size) {
    const float* in  = (const float*)d_in[0];
    const int*   tgt = (const int*)d_in[1];
    float*       out = (float*)d_out;
    (void)in_sizes; (void)n_in; (void)out_size;

    zero_k<<<(BB*CC*NI + 255) / 256, 256>>>();
    pass1_k<<<NBLK, TPB>>>(in, tgt);
    dim3 g(BB, 16);
    means_k<<<g, 256>>>();
    pass2_k<<<NBLK, TPB>>>(in, tgt);
    final_k<<<1, 32>>>(out);
}

// round 5
// speedup vs baseline: 1.5248x; 1.3266x over previous
#include <cuda_runtime.h>
#include <cuda_bf16.h>
#include <math.h>

// Problem constants (fixed by the reference setup)
#define BB 4
#define CC 32
#define NCP 16          // channel pairs
#define PP 262144       // 512*512 pixels per image
#define NI 100          // n_instances
#define CHUNK 2048      // pixels per block
#define TPB 512
#define CHUNKS_PER_IMG (PP/CHUNK)   // 128
#define NBLK (BB*CHUNKS_PER_IMG)    // 512

// Scratch (no device allocation allowed -> __device__ globals)
__device__ float g_sums[BB*CC*NI];   // [b][c][k]
__device__ int   g_counts[BB*NI];
__device__ float g_means[BB*CC*NI];  // [b][c][k]
__device__ float g_invc[BB*NI];
__device__ float g_var[BB];
__device__ float g_dist[BB];
__device__ float g_reg[BB];

__global__ void zero_k() {
    int i = blockIdx.x * blockDim.x + threadIdx.x;
    if (i < BB*CC*NI) g_sums[i] = 0.f;
    if (i < BB*NI)    g_counts[i] = 0;
    if (i < BB) { g_var[i] = 0.f; g_dist[i] = 0.f; g_reg[i] = 0.f; }
}

// -------- Pass 1: per-label sums (bf16x2 channel-pair atomics) + counts --------
__global__ __launch_bounds__(TPB) void pass1_k(const float* __restrict__ in,
                                               const int* __restrict__ tgt) {
    __shared__ __nv_bfloat162 ssum[NCP*NI];   // [cp*100+k]
    __shared__ int scnt[NI];

    int blk   = blockIdx.x;
    int b     = blk >> 7;           // /128
    int chunk = blk & 127;
    int p0    = chunk * CHUNK;
    int t     = threadIdx.x;

    for (int i = t; i < NCP*NI; i += TPB) ssum[i] = __nv_bfloat162(__float2bfloat16(0.f), __float2bfloat16(0.f));
    for (int i = t; i < NI;     i += TPB) scnt[i] = 0;
    __syncthreads();

    const int4* tg = (const int4*)(tgt + (size_t)b * PP + p0);
    int4 lv = tg[t];
    int lbl[4] = {lv.x, lv.y, lv.z, lv.w};
#pragma unroll
    for (int k = 0; k < 4; k++) atomicAdd(&scnt[lbl[k]], 1);

    const float* base = in + (size_t)b * CC * PP + p0;
#pragma unroll 2
    for (int cp = 0; cp < NCP; cp++) {
        const float4* pc0 = (const float4*)(base + (size_t)(2*cp)   * PP);
        const float4* pc1 = (const float4*)(base + (size_t)(2*cp+1) * PP);
        float4 v0 = pc0[t];
        float4 v1 = pc1[t];
        __nv_bfloat162 p0v = __floats2bfloat162_rn(v0.x, v1.x);
        __nv_bfloat162 p1v = __floats2bfloat162_rn(v0.y, v1.y);
        __nv_bfloat162 p2v = __floats2bfloat162_rn(v0.z, v1.z);
        __nv_bfloat162 p3v = __floats2bfloat162_rn(v0.w, v1.w);
        atomicAdd(&ssum[cp*NI + lbl[0]], p0v);
        atomicAdd(&ssum[cp*NI + lbl[1]], p1v);
        atomicAdd(&ssum[cp*NI + lbl[2]], p2v);
        atomicAdd(&ssum[cp*NI + lbl[3]], p3v);
    }
    __syncthreads();

    // flush: bf16x2 partials -> fp32 global accumulators
    float* gs = g_sums + (size_t)b * CC * NI;
    for (int i = t; i < NCP*NI; i += TPB) {
        int cp = i / NI;
        int k  = i - cp * NI;
        __nv_bfloat162 v = ssum[i];
        atomicAdd(&gs[(2*cp)   * NI + k], __bfloat162float(v.x));
        atomicAdd(&gs[(2*cp+1) * NI + k], __bfloat162float(v.y));
    }
    int* gc = g_counts + b * NI;
    for (int i = t; i < NI; i += TPB) atomicAdd(&gc[i], scnt[i]);
}

// -------- Middle: means, inv-counts, reg term, pairwise distance term --------
// grid = (4, 16), block = 256
__global__ __launch_bounds__(256) void means_k() {
    __shared__ float sm[NI*33];     // [k*33+c] padded: pairwise reads conflict-free
    __shared__ float red[8];

    int b = blockIdx.x;
    int t = threadIdx.x;

    for (int i = t; i < CC*NI; i += 256) {
        int c = i / NI;
        int k = i - c * NI;
        int cnt = g_counts[b*NI + k];
        float m = (cnt > 0) ? g_sums[(size_t)b*CC*NI + i] / (float)cnt : 0.f;
        sm[k*33 + c] = m;
        if (blockIdx.y == 0) g_means[(size_t)b*CC*NI + i] = m;
    }
    if (blockIdx.y == 0) {
        for (int k = t; k < NI; k += 256) {
            int cnt = g_counts[b*NI + k];
            g_invc[b*NI + k] = (cnt > 0) ? 1.f / (float)cnt : 0.f;
        }
    }
    __syncthreads();

    // reg term: sum_k ||mean_k||
    if (blockIdx.y == 0 && t < NI) {
        float s = 0.f;
#pragma unroll
        for (int c = 0; c < CC; c++) { float m = sm[t*33 + c]; s = fmaf(m, m, s); }
        atomicAdd(&g_reg[b], sqrtf(s));
    }

    // distance term over all (i,j), i != j
    float local = 0.f;
    for (int idx = blockIdx.y * 256 + t; idx < NI*NI; idx += gridDim.y * 256) {
        int i = idx / NI;
        int j = idx - i * NI;
        if (i != j) {
            float d2 = 0.f;
#pragma unroll
            for (int c = 0; c < CC; c++) {
                float d = sm[i*33 + c] - sm[j*33 + c];
                d2 = fmaf(d, d, d2);
            }
            float d = (d2 > 0.f) ? sqrtf(d2) : 1.f;   // matches jnp.where(d2>0, d2, 1)
            float h = fmaxf(4.f - d, 0.f);            // 2*DELTA_DIST = 4
            local += h * h;
        }
    }
#pragma unroll
    for (int o = 16; o > 0; o >>= 1) local += __shfl_down_sync(0xffffffffu, local, o);
    if ((t & 31) == 0) red[t >> 5] = local;
    __syncthreads();
    if (t < 32) {
        float v = (t < 8) ? red[t] : 0.f;
#pragma unroll
        for (int o = 4; o > 0; o >>= 1) v += __shfl_down_sync(0xffffffffu, v, o);
        if (t == 0) atomicAdd(&g_dist[b], v);
    }
}

// -------- Pass 2: variance term (register-resident per-pixel accumulators) --------
__global__ __launch_bounds__(TPB) void pass2_k(const float* __restrict__ in,
                                               const int* __restrict__ tgt) {
    __shared__ float smean[CC*NI];  // [c*100+k]
    __shared__ float sinv[NI];
    __shared__ float red[TPB/32];

    int blk   = blockIdx.x;
    int b     = blk >> 7;
    int chunk = blk & 127;
    int p0    = chunk * CHUNK;
    int t     = threadIdx.x;

    for (int i = t; i < CC*NI; i += TPB) smean[i] = g_means[(size_t)b*CC*NI + i];
    for (int i = t; i < NI;    i += TPB) sinv[i]  = g_invc[b*NI + i];
    __syncthreads();

    const int4* tg = (const int4*)(tgt + (size_t)b * PP + p0);
    int4 lv = tg[t];
    int lbl[4] = {lv.x, lv.y, lv.z, lv.w};

    float acc[4] = {0.f, 0.f, 0.f, 0.f};

    const float* base = in + (size_t)b * CC * PP + p0;
#pragma unroll 4
    for (int c = 0; c < CC; c++) {
        const float4* pc = (const float4*)(base + (size_t)c * PP);
        float4 v = pc[t];
        float d0 = v.x - smean[c*NI + lbl[0]];
        float d1 = v.y - smean[c*NI + lbl[1]];
        float d2 = v.z - smean[c*NI + lbl[2]];
        float d3 = v.w - smean[c*NI + lbl[3]];
        acc[0] = fmaf(d0, d0, acc[0]);
        acc[1] = fmaf(d1, d1, acc[1]);
        acc[2] = fmaf(d2, d2, acc[2]);
        acc[3] = fmaf(d3, d3, acc[3]);
    }

    float local = 0.f;
#pragma unroll
    for (int k = 0; k < 4; k++) {
        float n = sqrtf(acc[k]);
        float h = fmaxf(n - 0.75f, 0.f);   // DELTA_VAR
        local += h * h * sinv[lbl[k]];
    }
#pragma unroll
    for (int o = 16; o > 0; o >>= 1) local += __shfl_down_sync(0xffffffffu, local, o);
    if ((t & 31) == 0) red[t >> 5] = local;
    __syncthreads();
    if (t < 32) {
        float v = (t < TPB/32) ? red[t] : 0.f;
#pragma unroll
        for (int o = 16; o > 0; o >>= 1) v += __shfl_down_sync(0xffffffffu, v, o);
        if (t == 0) atomicAdd(&g_var[b], v);
    }
}

// -------- Final: combine terms, mean over batch --------
__global__ void final_k(float* __restrict__ out) {
    if (threadIdx.x == 0 && blockIdx.x == 0) {
        float s = 0.f;
#pragma unroll
        for (int b = 0; b < BB; b++) {
            float var_term  = g_var[b]  * (1.f / (float)NI);
            float dist_term = g_dist[b] * (1.f / (float)(NI * (NI - 1)));
            float reg_term  = g_reg[b]  * (1.f / (float)NI);
            s += var_term + dist_term + 0.001f * reg_term;   // ALPHA=BETA=1, GAMMA=1e-3
        }
        out[0] = s * (1.f / (float)BB);
    }
}

extern "C" void kernel_launch(void* const* d_in, const int* in_sizes, int n_in,
                              void* d_out, int out_size) {
    const float* in  = (const float*)d_in[0];
    const int*   tgt = (const int*)d_in[1];
    float*       out = (float*)d_out;
    (void)in_sizes; (void)n_in; (void)out_size;

    zero_k<<<(BB*CC*NI + 255) / 256, 256>>>();
    pass1_k<<<NBLK, TPB>>>(in, tgt);
    dim3 g(BB, 16);
    means_k<<<g, 256>>>();
    pass2_k<<<NBLK, TPB>>>(in, tgt);
    final_k<<<1, 32>>>(out);
}

// round 6
// speedup vs baseline: 1.6932x; 1.1105x over previous
#include <cuda_runtime.h>
#include <cuda_bf16.h>
#include <math.h>

// Problem constants (fixed by the reference setup)
#define BB 4
#define CC 32
#define NCP 16          // channel pairs
#define PP 262144       // 512*512 pixels per image
#define NI 100          // n_instances
#define CHUNK 2048      // pixels per block
#define TPB 512
#define NCOPY 4         // bank-sliced histogram copies
#define CHUNKS_PER_IMG (PP/CHUNK)   // 128
#define NBLK (BB*CHUNKS_PER_IMG)    // 512

// Scratch (no device allocation allowed -> __device__ globals)
__device__ float g_sums[BB*CC*NI];   // [b][c][k]
__device__ int   g_counts[BB*NI];
__device__ float g_means[BB*CC*NI];  // [b][c][k]
__device__ float g_invc[BB*NI];
__device__ float g_var[BB];
__device__ float g_dist[BB];
__device__ float g_reg[BB];

__global__ void zero_k() {
    int i = blockIdx.x * blockDim.x + threadIdx.x;
    if (i < BB*CC*NI) g_sums[i] = 0.f;
    if (i < BB*NI)    g_counts[i] = 0;
    if (i < BB) { g_var[i] = 0.f; g_dist[i] = 0.f; g_reg[i] = 0.f; }
}

// -------- Pass 1: per-label sums (bf16x2 atomics, 4-way bank-sliced) --------
__global__ __launch_bounds__(TPB) void pass1_k(const float* __restrict__ in,
                                               const int* __restrict__ tgt) {
    __shared__ __nv_bfloat162 ssum[NCP*NI*NCOPY];   // [(cp*100+k)*4 + copy]
    __shared__ int scnt[NI];

    int blk   = blockIdx.x;
    int b     = blk >> 7;           // /128
    int chunk = blk & 127;
    int p0    = chunk * CHUNK;
    int t     = threadIdx.x;
    int cpy   = t & (NCOPY-1);      // lane&3 == tid&3

    __nv_bfloat162 z2 = __nv_bfloat162(__float2bfloat16(0.f), __float2bfloat16(0.f));
    for (int i = t; i < NCP*NI*NCOPY; i += TPB) ssum[i] = z2;
    for (int i = t; i < NI;           i += TPB) scnt[i] = 0;
    __syncthreads();

    const int4* tg = (const int4*)(tgt + (size_t)b * PP + p0);
    int4 lv = tg[t];
    int lbl[4] = {lv.x, lv.y, lv.z, lv.w};
#pragma unroll
    for (int k = 0; k < 4; k++) atomicAdd(&scnt[lbl[k]], 1);

    // precompute sliced slot indices
    int s0 = lbl[0]*NCOPY + cpy;
    int s1 = lbl[1]*NCOPY + cpy;
    int s2 = lbl[2]*NCOPY + cpy;
    int s3 = lbl[3]*NCOPY + cpy;

    const float* base = in + (size_t)b * CC * PP + p0;
#pragma unroll 2
    for (int cp = 0; cp < NCP; cp++) {
        const float4* pc0 = (const float4*)(base + (size_t)(2*cp)   * PP);
        const float4* pc1 = (const float4*)(base + (size_t)(2*cp+1) * PP);
        float4 v0 = pc0[t];
        float4 v1 = pc1[t];
        __nv_bfloat162 p0v = __floats2bfloat162_rn(v0.x, v1.x);
        __nv_bfloat162 p1v = __floats2bfloat162_rn(v0.y, v1.y);
        __nv_bfloat162 p2v = __floats2bfloat162_rn(v0.z, v1.z);
        __nv_bfloat162 p3v = __floats2bfloat162_rn(v0.w, v1.w);
        int cb = cp*NI*NCOPY;
        atomicAdd(&ssum[cb + s0], p0v);
        atomicAdd(&ssum[cb + s1], p1v);
        atomicAdd(&ssum[cb + s2], p2v);
        atomicAdd(&ssum[cb + s3], p3v);
    }
    __syncthreads();

    // flush: reduce 4 copies, bf16 -> fp32 global accumulators
    float* gs = g_sums + (size_t)b * CC * NI;
    for (int i = t; i < NCP*NI; i += TPB) {
        int cp = i / NI;
        int k  = i - cp * NI;
        float sx = 0.f, sy = 0.f;
#pragma unroll
        for (int c = 0; c < NCOPY; c++) {
            __nv_bfloat162 v = ssum[i*NCOPY + c];
            sx += __bfloat162float(v.x);
            sy += __bfloat162float(v.y);
        }
        atomicAdd(&gs[(2*cp)   * NI + k], sx);
        atomicAdd(&gs[(2*cp+1) * NI + k], sy);
    }
    int* gc = g_counts + b * NI;
    for (int i = t; i < NI; i += TPB) atomicAdd(&gc[i], scnt[i]);
}

// -------- Middle: means, inv-counts, reg term, pairwise distance term --------
// grid = (4, 16), block = 256
__global__ __launch_bounds__(256) void means_k() {
    __shared__ float sm[NI*33];     // [k*33+c] padded: pairwise reads conflict-free
    __shared__ float red[8];

    int b = blockIdx.x;
    int t = threadIdx.x;

    for (int i = t; i < CC*NI; i += 256) {
        int c = i / NI;
        int k = i - c * NI;
        int cnt = g_counts[b*NI + k];
        float m = (cnt > 0) ? g_sums[(size_t)b*CC*NI + i] / (float)cnt : 0.f;
        sm[k*33 + c] = m;
        if (blockIdx.y == 0) g_means[(size_t)b*CC*NI + i] = m;
    }
    if (blockIdx.y == 0) {
        for (int k = t; k < NI; k += 256) {
            int cnt = g_counts[b*NI + k];
            g_invc[b*NI + k] = (cnt > 0) ? 1.f / (float)cnt : 0.f;
        }
    }
    __syncthreads();

    // reg term: sum_k ||mean_k||
    if (blockIdx.y == 0 && t < NI) {
        float s = 0.f;
#pragma unroll
        for (int c = 0; c < CC; c++) { float m = sm[t*33 + c]; s = fmaf(m, m, s); }
        atomicAdd(&g_reg[b], sqrtf(s));
    }

    // distance term over all (i,j), i != j
    float local = 0.f;
    for (int idx = blockIdx.y * 256 + t; idx < NI*NI; idx += gridDim.y * 256) {
        int i = idx / NI;
        int j = idx - i * NI;
        if (i != j) {
            float d2 = 0.f;
#pragma unroll
            for (int c = 0; c < CC; c++) {
                float d = sm[i*33 + c] - sm[j*33 + c];
                d2 = fmaf(d, d, d2);
            }
            float d = (d2 > 0.f) ? sqrtf(d2) : 1.f;   // matches jnp.where(d2>0, d2, 1)
            float h = fmaxf(4.f - d, 0.f);            // 2*DELTA_DIST = 4
            local += h * h;
        }
    }
#pragma unroll
    for (int o = 16; o > 0; o >>= 1) local += __shfl_down_sync(0xffffffffu, local, o);
    if ((t & 31) == 0) red[t >> 5] = local;
    __syncthreads();
    if (t < 32) {
        float v = (t < 8) ? red[t] : 0.f;
#pragma unroll
        for (int o = 4; o > 0; o >>= 1) v += __shfl_down_sync(0xffffffffu, v, o);
        if (t == 0) atomicAdd(&g_dist[b], v);
    }
}

// -------- Pass 2: variance term (register-resident per-pixel accumulators) --------
__global__ __launch_bounds__(TPB) void pass2_k(const float* __restrict__ in,
                                               const int* __restrict__ tgt) {
    __shared__ float smean[CC*NI];  // [c*100+k]
    __shared__ float sinv[NI];
    __shared__ float red[TPB/32];

    int blk   = blockIdx.x;
    int b     = blk >> 7;
    int chunk = blk & 127;
    int p0    = chunk * CHUNK;
    int t     = threadIdx.x;

    for (int i = t; i < CC*NI; i += TPB) smean[i] = g_means[(size_t)b*CC*NI + i];
    for (int i = t; i < NI;    i += TPB) sinv[i]  = g_invc[b*NI + i];
    __syncthreads();

    const int4* tg = (const int4*)(tgt + (size_t)b * PP + p0);
    int4 lv = tg[t];
    int lbl[4] = {lv.x, lv.y, lv.z, lv.w};

    float acc[4] = {0.f, 0.f, 0.f, 0.f};

    const float* base = in + (size_t)b * CC * PP + p0;
#pragma unroll 4
    for (int c = 0; c < CC; c++) {
        const float4* pc = (const float4*)(base + (size_t)c * PP);
        float4 v = pc[t];
        float d0 = v.x - smean[c*NI + lbl[0]];
        float d1 = v.y - smean[c*NI + lbl[1]];
        float d2 = v.z - smean[c*NI + lbl[2]];
        float d3 = v.w - smean[c*NI + lbl[3]];
        acc[0] = fmaf(d0, d0, acc[0]);
        acc[1] = fmaf(d1, d1, acc[1]);
        acc[2] = fmaf(d2, d2, acc[2]);
        acc[3] = fmaf(d3, d3, acc[3]);
    }

    float local = 0.f;
#pragma unroll
    for (int k = 0; k < 4; k++) {
        float n = sqrtf(acc[k]);
        float h = fmaxf(n - 0.75f, 0.f);   // DELTA_VAR
        local += h * h * sinv[lbl[k]];
    }
#pragma unroll
    for (int o = 16; o > 0; o >>= 1) local += __shfl_down_sync(0xffffffffu, local, o);
    if ((t & 31) == 0) red[t >> 5] = local;
    __syncthreads();
    if (t < 32) {
        float v = (t < TPB/32) ? red[t] : 0.f;
#pragma unroll
        for (int o = 16; o > 0; o >>= 1) v += __shfl_down_sync(0xffffffffu, v, o);
        if (t == 0) atomicAdd(&g_var[b], v);
    }
}

// -------- Final: combine terms, mean over batch --------
__global__ void final_k(float* __restrict__ out) {
    if (threadIdx.x == 0 && blockIdx.x == 0) {
        float s = 0.f;
#pragma unroll
        for (int b = 0; b < BB; b++) {
            float var_term  = g_var[b]  * (1.f / (float)NI);
            float dist_term = g_dist[b] * (1.f / (float)(NI * (NI - 1)));
            float reg_term  = g_reg[b]  * (1.f / (float)NI);
            s += var_term + dist_term + 0.001f * reg_term;   // ALPHA=BETA=1, GAMMA=1e-3
        }
        out[0] = s * (1.f / (float)BB);
    }
}

extern "C" void kernel_launch(void* const* d_in, const int* in_sizes, int n_in,
                              void* d_out, int out_size) {
    const float* in  = (const float*)d_in[0];
    const int*   tgt = (const int*)d_in[1];
    float*       out = (float*)d_out;
    (void)in_sizes; (void)n_in; (void)out_size;

    zero_k<<<(BB*CC*NI + 255) / 256, 256>>>();
    pass1_k<<<NBLK, TPB>>>(in, tgt);
    dim3 g(BB, 16);
    means_k<<<g, 256>>>();
    pass2_k<<<NBLK, TPB>>>(in, tgt);
    final_k<<<1, 32>>>(out);
}

// round 7
// speedup vs baseline: 1.7772x; 1.0496x over previous
#include <cuda_runtime.h>
#include <cuda_bf16.h>
#include <math.h>

// Problem constants (fixed by the reference setup)
#define BB 4
#define CC 32
#define NCP 16          // channel pairs
#define PP 262144       // 512*512 pixels per image
#define NI 100          // n_instances
#define CHUNK 2048      // pixels per block
#define TPB 512
#define NCOPY 8         // bank-sliced histogram copies
#define CHUNKS_PER_IMG (PP/CHUNK)   // 128
#define NBLK (BB*CHUNKS_PER_IMG)    // 512
#define NBLK2 (NBLK + BB)           // 516: 512 variance + 4 distance blocks

// Scratch (no device allocation allowed -> __device__ globals).
// All accumulators are zero at module load; the ticket block of pass2_k
// re-zeros them at the end of every run so each replay starts clean.
__device__ float g_sums[BB*CC*NI];   // [b][c][k]
__device__ int   g_counts[BB*NI];
__device__ float g_var[BB];
__device__ float g_dist[BB];
__device__ float g_reg[BB];
__device__ unsigned int g_ticket;

// -------- Pass 1: per-label sums (bf16x2 atomics, 8-way bank-sliced) --------
__global__ __launch_bounds__(TPB) void pass1_k(const float* __restrict__ in,
                                               const int* __restrict__ tgt) {
    __shared__ __nv_bfloat162 ssum[NCP*NI*NCOPY];   // [(cp*100+k)*8 + copy]
    __shared__ int scnt[NI];

    int blk   = blockIdx.x;
    int b     = blk >> 7;           // /128
    int chunk = blk & 127;
    int p0    = chunk * CHUNK;
    int t     = threadIdx.x;
    int cpy   = t & (NCOPY-1);

    __nv_bfloat162 z2 = __nv_bfloat162(__float2bfloat16(0.f), __float2bfloat16(0.f));
    for (int i = t; i < NCP*NI*NCOPY; i += TPB) ssum[i] = z2;
    for (int i = t; i < NI;           i += TPB) scnt[i] = 0;
    __syncthreads();

    const int4* tg = (const int4*)(tgt + (size_t)b * PP + p0);
    int4 lv = tg[t];
    int lbl[4] = {lv.x, lv.y, lv.z, lv.w};
#pragma unroll
    for (int k = 0; k < 4; k++) atomicAdd(&scnt[lbl[k]], 1);

    int s0 = lbl[0]*NCOPY + cpy;
    int s1 = lbl[1]*NCOPY + cpy;
    int s2 = lbl[2]*NCOPY + cpy;
    int s3 = lbl[3]*NCOPY + cpy;

    const float* base = in + (size_t)b * CC * PP + p0;
#pragma unroll 2
    for (int cp = 0; cp < NCP; cp++) {
        const float4* pc0 = (const float4*)(base + (size_t)(2*cp)   * PP);
        const float4* pc1 = (const float4*)(base + (size_t)(2*cp+1) * PP);
        float4 v0 = pc0[t];
        float4 v1 = pc1[t];
        __nv_bfloat162 p0v = __floats2bfloat162_rn(v0.x, v1.x);
        __nv_bfloat162 p1v = __floats2bfloat162_rn(v0.y, v1.y);
        __nv_bfloat162 p2v = __floats2bfloat162_rn(v0.z, v1.z);
        __nv_bfloat162 p3v = __floats2bfloat162_rn(v0.w, v1.w);
        int cb = cp*NI*NCOPY;
        atomicAdd(&ssum[cb + s0], p0v);
        atomicAdd(&ssum[cb + s1], p1v);
        atomicAdd(&ssum[cb + s2], p2v);
        atomicAdd(&ssum[cb + s3], p3v);
    }
    __syncthreads();

    // flush: reduce copies, bf16 -> fp32 global accumulators
    float* gs = g_sums + (size_t)b * CC * NI;
    for (int i = t; i < NCP*NI; i += TPB) {
        int cp = i / NI;
        int k  = i - cp * NI;
        float sx = 0.f, sy = 0.f;
#pragma unroll
        for (int c = 0; c < NCOPY; c++) {
            __nv_bfloat162 v = ssum[i*NCOPY + c];
            sx += __bfloat162float(v.x);
            sy += __bfloat162float(v.y);
        }
        atomicAdd(&gs[(2*cp)   * NI + k], sx);
        atomicAdd(&gs[(2*cp+1) * NI + k], sy);
    }
    int* gc = g_counts + b * NI;
    for (int i = t; i < NI; i += TPB) atomicAdd(&gc[i], scnt[i]);
}

// -------- Pass 2 (fused): variance blocks + distance/reg blocks + final --------
__global__ __launch_bounds__(TPB) void pass2_k(const float* __restrict__ in,
                                               const int* __restrict__ tgt,
                                               float* __restrict__ out) {
    __shared__ float sh[NI*33 + NI + 32];
    __shared__ bool s_last;
    int blk = blockIdx.x;
    int t   = threadIdx.x;

    if (blk < NBLK) {
        // ---- variance term ----
        float* smean = sh;                 // [c*100+k]
        float* sinv  = sh + CC*NI;         // [k]
        float* red   = sh + CC*NI + NI;

        int b  = blk >> 7;
        int p0 = (blk & 127) * CHUNK;

        const float* gs = g_sums + (size_t)b * CC * NI;
        const int*   gc = g_counts + b * NI;
        for (int i = t; i < NI; i += TPB) {
            int cnt = gc[i];
            sinv[i] = (cnt > 0) ? 1.f / (float)cnt : 0.f;
        }
        for (int i = t; i < CC*NI; i += TPB) {
            int c = i / NI;
            int k = i - c * NI;
            int cnt = gc[k];
            smean[i] = (cnt > 0) ? gs[i] / (float)cnt : 0.f;
        }
        __syncthreads();

        const int4* tg = (const int4*)(tgt + (size_t)b * PP + p0);
        int4 lv = tg[t];
        int lbl[4] = {lv.x, lv.y, lv.z, lv.w};

        float acc[4] = {0.f, 0.f, 0.f, 0.f};
        const float* base = in + (size_t)b * CC * PP + p0;
#pragma unroll 4
        for (int c = 0; c < CC; c++) {
            const float4* pc = (const float4*)(base + (size_t)c * PP);
            float4 v = pc[t];
            float d0 = v.x - smean[c*NI + lbl[0]];
            float d1 = v.y - smean[c*NI + lbl[1]];
            float d2 = v.z - smean[c*NI + lbl[2]];
            float d3 = v.w - smean[c*NI + lbl[3]];
            acc[0] = fmaf(d0, d0, acc[0]);
            acc[1] = fmaf(d1, d1, acc[1]);
            acc[2] = fmaf(d2, d2, acc[2]);
            acc[3] = fmaf(d3, d3, acc[3]);
        }

        float local = 0.f;
#pragma unroll
        for (int k = 0; k < 4; k++) {
            float n = sqrtf(acc[k]);
            float h = fmaxf(n - 0.75f, 0.f);   // DELTA_VAR
            local += h * h * sinv[lbl[k]];
        }
#pragma unroll
        for (int o = 16; o > 0; o >>= 1) local += __shfl_down_sync(0xffffffffu, local, o);
        if ((t & 31) == 0) red[t >> 5] = local;
        __syncthreads();
        if (t < 32) {
            float v = (t < TPB/32) ? red[t] : 0.f;
#pragma unroll
            for (int o = 16; o > 0; o >>= 1) v += __shfl_down_sync(0xffffffffu, v, o);
            if (t == 0) atomicAdd(&g_var[b], v);
        }
    } else {
        // ---- distance + reg terms (one block per batch image) ----
        float* sm = sh;                    // [k*33+c] padded
        int b = blk - NBLK;

        const float* gs = g_sums + (size_t)b * CC * NI;
        const int*   gc = g_counts + b * NI;
        for (int i = t; i < CC*NI; i += TPB) {
            int c = i / NI;
            int k = i - c * NI;
            int cnt = gc[k];
            sm[k*33 + c] = (cnt > 0) ? gs[i] / (float)cnt : 0.f;
        }
        if (t == 0) sh[NI*33 + NI] = 0.f;   // reg accumulator
        __syncthreads();

        // reg term
        if (t < NI) {
            float s = 0.f;
#pragma unroll
            for (int c = 0; c < CC; c++) { float m = sm[t*33 + c]; s = fmaf(m, m, s); }
            atomicAdd(&sh[NI*33 + NI], sqrtf(s));
        }

        // distance term
        float local = 0.f;
        for (int idx = t; idx < NI*NI; idx += TPB) {
            int i = idx / NI;
            int j = idx - i * NI;
            if (i != j) {
                float d2 = 0.f;
#pragma unroll
                for (int c = 0; c < CC; c++) {
                    float d = sm[i*33 + c] - sm[j*33 + c];
                    d2 = fmaf(d, d, d2);
                }
                float d = (d2 > 0.f) ? sqrtf(d2) : 1.f;   // jnp.where(d2>0, d2, 1)
                float h = fmaxf(4.f - d, 0.f);            // 2*DELTA_DIST
                local += h * h;
            }
        }
        float* red = sh + NI*33;
#pragma unroll
        for (int o = 16; o > 0; o >>= 1) local += __shfl_down_sync(0xffffffffu, local, o);
        if ((t & 31) == 0) red[t >> 5] = local;
        __syncthreads();
        if (t < 32) {
            float v = (t < TPB/32) ? red[t] : 0.f;
#pragma unroll
            for (int o = 16; o > 0; o >>= 1) v += __shfl_down_sync(0xffffffffu, v, o);
            if (t == 0) {
                g_dist[b] = v;                 // exclusive owner: plain store
                g_reg[b]  = sh[NI*33 + NI];
            }
        }
    }

    // ---- ticket: last block finishes -> final combine + cleanup for next replay ----
    __syncthreads();
    if (t == 0) {
        __threadfence();
        unsigned r = atomicAdd(&g_ticket, 1u);
        s_last = (r == NBLK2 - 1);
    }
    __syncthreads();
    if (s_last) {
        if (t == 0) {
            float s = 0.f;
#pragma unroll
            for (int b = 0; b < BB; b++) {
                float var_term  = g_var[b]  * (1.f / (float)NI);
                float dist_term = g_dist[b] * (1.f / (float)(NI * (NI - 1)));
                float reg_term  = g_reg[b]  * (1.f / (float)NI);
                s += var_term + dist_term + 0.001f * reg_term;
            }
            out[0] = s * (1.f / (float)BB);
        }
        // cleanup (runs concurrently with t0's out computation; disjoint arrays)
        for (int i = t; i < BB*CC*NI; i += TPB) g_sums[i] = 0.f;
        for (int i = t; i < BB*NI;    i += TPB) g_counts[i] = 0;
        __syncthreads();
        if (t < BB) { g_var[t] = 0.f; g_dist[t] = 0.f; g_reg[t] = 0.f; }
        if (t == 0) g_ticket = 0u;
    }
}

extern "C" void kernel_launch(void* const* d_in, const int* in_sizes, int n_in,
                              void* d_out, int out_size) {
    const float* in  = (const float*)d_in[0];
    const int*   tgt = (const int*)d_in[1];
    float*       out = (float*)d_out;
    (void)in_sizes; (void)n_in; (void)out_size;

    pass1_k<<<NBLK, TPB>>>(in, tgt);
    pass2_k<<<NBLK2, TPB>>>(in, tgt, out);
}